// round 12
// baseline (speedup 1.0000x reference)
#include <cuda_runtime.h>
#include <cuda_fp16.h>

#define RES 256
#define NA  180
#define NB  4
#define PW  257            // x0p in [0,256]
#define PH  257            // y0p in [0,256]
#define NPIX (PH*PW)

// Corner-packed fp16 images, all 4 batches in 32 bytes per padded pixel.
//   a.x = h2(b0.v00,b0.v01)  a.y = h2(b0.v10,b0.v11)
//   a.z/a.w = batch1, b.* = batches 2,3.
// vXY = img[y0+X][x0+Y], OOB -> 0 (zero border = reference's validity mask).
// g_PT is the same packing of the TRANSPOSED image at transposed coords:
//   g_PT[x0p*PW + y0p] = (v00, v10, v01, v11)  (middle corners swapped).
// Sampling g_PT at swapped (gy,gx) with the standard bilerp formula yields a
// bit-identical bilinear sample; used for steep angles to keep the warp
// footprint's long axis along x (4x cheaper in 128B lines).
struct __align__(32) Px { uint4 a, b; };
__device__ Px g_P [NPIX];
__device__ Px g_PT[NPIX];

__device__ __forceinline__ unsigned pack2(float a, float b) {
    __half2 h = __floats2half2_rn(a, b);
    return *reinterpret_cast<unsigned*>(&h);
}
__device__ __forceinline__ float2 unpack2(unsigned u) {
    __half2 h = *reinterpret_cast<__half2*>(&u);
    return __half22float2(h);
}

// 256-bit global load (sm_100+).
__device__ __forceinline__ void ldg256(const Px* p, uint4& a, uint4& b) {
    asm volatile("ld.global.nc.v8.u32 {%0,%1,%2,%3,%4,%5,%6,%7}, [%8];"
                 : "=r"(a.x), "=r"(a.y), "=r"(a.z), "=r"(a.w),
                   "=r"(b.x), "=r"(b.y), "=r"(b.z), "=r"(b.w)
                 : "l"(p));
}

// Prep: build both corner-packed arrays. One thread per padded pixel.
__global__ __launch_bounds__(256) void prep_kernel(const float* __restrict__ imgs)
{
    int idx = blockIdx.x * blockDim.x + threadIdx.x;
    if (idx >= NPIX) return;
    const int xp = idx % PW;
    const int yp = idx / PW;
    const int yt = yp - 1, yb = yp;
    const int xl = xp - 1, xr = xp;

    float v[NB][4];
    #pragma unroll
    for (int b = 0; b < NB; ++b) {
        const float* im = imgs + (size_t)b * RES * RES;
        const bool vt = ((unsigned)yt < RES), vb = ((unsigned)yb < RES);
        const bool vl = ((unsigned)xl < RES), vr = ((unsigned)xr < RES);
        v[b][0] = (vt && vl) ? im[yt * RES + xl] : 0.0f;   // v00
        v[b][1] = (vt && vr) ? im[yt * RES + xr] : 0.0f;   // v01
        v[b][2] = (vb && vl) ? im[yb * RES + xl] : 0.0f;   // v10
        v[b][3] = (vb && vr) ? im[yb * RES + xr] : 0.0f;   // v11
    }
    Px px;
    px.a.x = pack2(v[0][0], v[0][1]);  px.a.y = pack2(v[0][2], v[0][3]);
    px.a.z = pack2(v[1][0], v[1][1]);  px.a.w = pack2(v[1][2], v[1][3]);
    px.b.x = pack2(v[2][0], v[2][1]);  px.b.y = pack2(v[2][2], v[2][3]);
    px.b.z = pack2(v[3][0], v[3][1]);  px.b.w = pack2(v[3][2], v[3][3]);
    g_P[idx] = px;

    // Transposed entry: middle corners swapped, transposed location.
    Px pt;
    pt.a.x = pack2(v[0][0], v[0][2]);  pt.a.y = pack2(v[0][1], v[0][3]);
    pt.a.z = pack2(v[1][0], v[1][2]);  pt.a.w = pack2(v[1][1], v[1][3]);
    pt.b.x = pack2(v[2][0], v[2][2]);  pt.b.y = pack2(v[2][1], v[2][3]);
    pt.b.z = pack2(v[3][0], v[3][2]);  pt.b.w = pack2(v[3][1], v[3][3]);
    g_PT[xp * PW + yp] = pt;
}

// fp32 bilerp from packed (v00,v01)/(v10,v11) words.
__device__ __forceinline__ void bilerp_acc(unsigned top, unsigned bot,
                                           float wx, float wy, float& acc)
{
    const float2 T = unpack2(top);
    const float2 B = unpack2(bot);
    const float ft = fmaf(wx, T.y - T.x, T.x);
    const float fb = fmaf(wx, B.y - B.x, B.x);
    acc += fmaf(wy, fb - ft, ft);
}

// Block = 256 threads (8 warps). Warp tile: 8 rays x 4 t-phases, 64 iters.
// Grid: (angle, ray group) = (180, 4).
__global__ __launch_bounds__(256) void radon_kernel(
    const float* __restrict__ angles,
    const float* __restrict__ rays,
    float* __restrict__ out)
{
    const int tid  = threadIdx.x;
    const int lane = tid & 31;
    const int warp = tid >> 5;        // 0..7
    const int r8   = lane & 7;        // ray within warp tile
    const int t4   = lane >> 3;       // t-phase 0..3
    const int a    = blockIdx.x;      // angle
    const int rg   = blockIdx.y;      // ray group 0..3
    const int ray  = rg * 64 + warp * 8 + r8;

    const float4 r4 = __ldg(reinterpret_cast<const float4*>(rays) + ray);
    float s, c;
    sincosf(__ldg(angles + a), &s, &c);

    const float rsx = r4.x * c - r4.y * s;
    const float rsy = r4.x * s + r4.y * c;
    const float dx  = (r4.z * c - r4.w * s) - rsx;
    const float dy  = (r4.z * s + r4.w * c) - rsy;

    const float inv_n = 1.0f / RES;
    const float tp = (float)t4 + 0.5f;
    // +128.5 folds image-center offset (127.5) and the +1 padding shift.
    float gx = rsx + 128.5f + dx * inv_n * tp;
    float gy = rsy + 128.5f + dy * inv_n * tp;
    float sx4 = dx * inv_n * 4.0f;
    float sy4 = dy * inv_n * 4.0f;

    // Steep angles: swap coordinates and use the transposed array so the
    // warp footprint's long axis lies along x (fewer 128B lines). The loop
    // body is identical; branch is uniform per block.
    const Px* __restrict__ P = g_P;
    if (fabsf(s) > fabsf(c)) {
        float t;
        t = gx; gx = gy; gy = t;
        t = sx4; sx4 = sy4; sy4 = t;
        P = g_PT;
    }

    float acc0 = 0.f, acc1 = 0.f, acc2 = 0.f, acc3 = 0.f;

    #pragma unroll 8
    for (int i = 0; i < 64; ++i) {
        const int x0 = __float2int_rd(gx);
        const int y0 = __float2int_rd(gy);
        const float wx = gx - (float)x0;
        const float wy = gy - (float)y0;
        const int idx = y0 * PW + x0;

        uint4 qa, qb;
        ldg256(P + idx, qa, qb);

        bilerp_acc(qa.x, qa.y, wx, wy, acc0);
        bilerp_acc(qa.z, qa.w, wx, wy, acc1);
        bilerp_acc(qb.x, qb.y, wx, wy, acc2);
        bilerp_acc(qb.z, qb.w, wx, wy, acc3);

        gx += sx4;
        gy += sy4;
    }

    // Reduce the 4 t-phases of each ray (lanes l, l+8, l+16, l+24).
    acc0 += __shfl_xor_sync(0xFFFFFFFFu, acc0, 8);
    acc0 += __shfl_xor_sync(0xFFFFFFFFu, acc0, 16);
    acc1 += __shfl_xor_sync(0xFFFFFFFFu, acc1, 8);
    acc1 += __shfl_xor_sync(0xFFFFFFFFu, acc1, 16);
    acc2 += __shfl_xor_sync(0xFFFFFFFFu, acc2, 8);
    acc2 += __shfl_xor_sync(0xFFFFFFFFu, acc2, 16);
    acc3 += __shfl_xor_sync(0xFFFFFFFFu, acc3, 8);
    acc3 += __shfl_xor_sync(0xFFFFFFFFu, acc3, 16);

    if (t4 == 0) {
        const float step = (r4.w - r4.y) * inv_n;   // L / n_steps
        const int base = a * RES + ray;
        out[0 * NA * RES + base] = acc0 * step;
        out[1 * NA * RES + base] = acc1 * step;
        out[2 * NA * RES + base] = acc2 * step;
        out[3 * NA * RES + base] = acc3 * step;
    }
}

extern "C" void kernel_launch(void* const* d_in, const int* in_sizes, int n_in,
                              void* d_out, int out_size)
{
    const float* imgs   = (const float*)d_in[0];   // [4,256,256]
    const float* angles = (const float*)d_in[1];   // [180]
    const float* rays   = (const float*)d_in[2];   // [256,4]
    float* out          = (float*)d_out;           // [4,180,256]

    prep_kernel<<<(NPIX + 255) / 256, 256>>>(imgs);

    dim3 grid(NA, 4);
    radon_kernel<<<grid, 256>>>(angles, rays, out);
}

// round 13
// speedup vs baseline: 1.0024x; 1.0024x over previous
#include <cuda_runtime.h>
#include <cuda_fp16.h>

#define RES 256
#define NA  180
#define NB  4
#define PW  257            // x0p in [0,256]
#define PH  257            // y0p in [0,256]
#define NPIX (PH*PW)

// Corner-packed fp16 images, all 4 batches in 32 bytes per padded pixel.
//   a.x = h2(b0.v00,b0.v01)  a.y = h2(b0.v10,b0.v11)
//   a.z/a.w = batch1, b.* = batches 2,3.
// vXY = img[y0+X][x0+Y], OOB -> 0 (zero border = reference's validity mask).
struct __align__(32) Px { uint4 a, b; };
__device__ Px g_P[NPIX];

__device__ __forceinline__ unsigned pack2(float a, float b) {
    __half2 h = __floats2half2_rn(a, b);
    return *reinterpret_cast<unsigned*>(&h);
}
__device__ __forceinline__ float2 unpack2(unsigned u) {
    __half2 h = *reinterpret_cast<__half2*>(&u);
    return __half22float2(h);
}

// 256-bit global load (sm_100+).
__device__ __forceinline__ void ldg256(const Px* p, uint4& a, uint4& b) {
    asm volatile("ld.global.nc.v8.u32 {%0,%1,%2,%3,%4,%5,%6,%7}, [%8];"
                 : "=r"(a.x), "=r"(a.y), "=r"(a.z), "=r"(a.w),
                   "=r"(b.x), "=r"(b.y), "=r"(b.z), "=r"(b.w)
                 : "l"(p));
}

// Prep: one thread per (pixel, batch). 4 scalar loads, one coalesced 8B store.
// Thread t -> pixel idx = t>>2, batch b = t&3; stores the b-th uint2 of Px.
__global__ __launch_bounds__(256) void prep_kernel(const float* __restrict__ imgs)
{
    int t = blockIdx.x * blockDim.x + threadIdx.x;
    if (t >= NPIX * NB) return;
    const int b   = t & 3;
    const int idx = t >> 2;
    const int xp = idx % PW;
    const int yp = idx / PW;
    const int yt = yp - 1, yb = yp;
    const int xl = xp - 1, xr = xp;

    const float* im = imgs + (size_t)b * RES * RES;
    const bool vt = ((unsigned)yt < RES), vb = ((unsigned)yb < RES);
    const bool vl = ((unsigned)xl < RES), vr = ((unsigned)xr < RES);
    const float v00 = (vt && vl) ? __ldg(im + yt * RES + xl) : 0.0f;
    const float v01 = (vt && vr) ? __ldg(im + yt * RES + xr) : 0.0f;
    const float v10 = (vb && vl) ? __ldg(im + yb * RES + xl) : 0.0f;
    const float v11 = (vb && vr) ? __ldg(im + yb * RES + xr) : 0.0f;

    uint2 w;
    w.x = pack2(v00, v01);
    w.y = pack2(v10, v11);
    reinterpret_cast<uint2*>(&g_P[idx])[b] = w;
}

// fp32 bilerp from packed (v00,v01)/(v10,v11) words.
__device__ __forceinline__ void bilerp_acc(unsigned top, unsigned bot,
                                           float wx, float wy, float& acc)
{
    const float2 T = unpack2(top);
    const float2 B = unpack2(bot);
    const float ft = fmaf(wx, T.y - T.x, T.x);
    const float fb = fmaf(wx, B.y - B.x, B.x);
    acc += fmaf(wy, fb - ft, ft);
}

// Block = 128 threads (4 warps). Warp tile: 8 rays x 4 t-phases, 64 iters.
// Grid: (angle, ray group) = (180, 8). Direct stores, no atomics.
__global__ __launch_bounds__(128) void radon_kernel(
    const float* __restrict__ angles,
    const float* __restrict__ rays,
    float* __restrict__ out)
{
    const int tid  = threadIdx.x;
    const int lane = tid & 31;
    const int warp = tid >> 5;        // 0..3
    const int r8   = lane & 7;        // ray within warp tile
    const int t4   = lane >> 3;       // t-phase 0..3
    const int a    = blockIdx.x;      // angle
    const int rg   = blockIdx.y;      // ray group 0..7
    const int ray  = rg * 32 + warp * 8 + r8;

    const float4 r4 = __ldg(reinterpret_cast<const float4*>(rays) + ray);
    float s, c;
    sincosf(__ldg(angles + a), &s, &c);

    const float rsx = r4.x * c - r4.y * s;
    const float rsy = r4.x * s + r4.y * c;
    const float dx  = (r4.z * c - r4.w * s) - rsx;
    const float dy  = (r4.z * s + r4.w * c) - rsy;

    const float inv_n = 1.0f / RES;
    const float tp = (float)t4 + 0.5f;
    // +128.5 folds image-center offset (127.5) and the +1 padding shift.
    float gx = rsx + 128.5f + dx * inv_n * tp;
    float gy = rsy + 128.5f + dy * inv_n * tp;
    const float sx4 = dx * inv_n * 4.0f;
    const float sy4 = dy * inv_n * 4.0f;

    float acc0 = 0.f, acc1 = 0.f, acc2 = 0.f, acc3 = 0.f;

    #pragma unroll 8
    for (int i = 0; i < 64; ++i) {
        const int x0 = __float2int_rd(gx);
        const int y0 = __float2int_rd(gy);
        const float wx = gx - (float)x0;
        const float wy = gy - (float)y0;
        const int idx = y0 * PW + x0;

        uint4 qa, qb;
        ldg256(g_P + idx, qa, qb);

        bilerp_acc(qa.x, qa.y, wx, wy, acc0);
        bilerp_acc(qa.z, qa.w, wx, wy, acc1);
        bilerp_acc(qb.x, qb.y, wx, wy, acc2);
        bilerp_acc(qb.z, qb.w, wx, wy, acc3);

        gx += sx4;
        gy += sy4;
    }

    // Reduce the 4 t-phases of each ray (lanes l, l+8, l+16, l+24).
    acc0 += __shfl_xor_sync(0xFFFFFFFFu, acc0, 8);
    acc0 += __shfl_xor_sync(0xFFFFFFFFu, acc0, 16);
    acc1 += __shfl_xor_sync(0xFFFFFFFFu, acc1, 8);
    acc1 += __shfl_xor_sync(0xFFFFFFFFu, acc1, 16);
    acc2 += __shfl_xor_sync(0xFFFFFFFFu, acc2, 8);
    acc2 += __shfl_xor_sync(0xFFFFFFFFu, acc2, 16);
    acc3 += __shfl_xor_sync(0xFFFFFFFFu, acc3, 8);
    acc3 += __shfl_xor_sync(0xFFFFFFFFu, acc3, 16);

    if (t4 == 0) {
        const float step = (r4.w - r4.y) * inv_n;   // L / n_steps
        const int base = a * RES + ray;
        out[0 * NA * RES + base] = acc0 * step;
        out[1 * NA * RES + base] = acc1 * step;
        out[2 * NA * RES + base] = acc2 * step;
        out[3 * NA * RES + base] = acc3 * step;
    }
}

extern "C" void kernel_launch(void* const* d_in, const int* in_sizes, int n_in,
                              void* d_out, int out_size)
{
    const float* imgs   = (const float*)d_in[0];   // [4,256,256]
    const float* angles = (const float*)d_in[1];   // [180]
    const float* rays   = (const float*)d_in[2];   // [256,4]
    float* out          = (float*)d_out;           // [4,180,256]

    prep_kernel<<<(NPIX * NB + 255) / 256, 256>>>(imgs);

    dim3 grid(NA, 8);
    radon_kernel<<<grid, 128>>>(angles, rays, out);
}

// round 14
// speedup vs baseline: 1.0193x; 1.0169x over previous
#include <cuda_runtime.h>
#include <cuda_fp16.h>

#define RES 256
#define NA  180
#define NB  4
#define PW  257            // x0p in [0,256]
#define PH  257            // y0p in [0,256]
#define NPIX (PH*PW)

// Corner-packed fp16 images, all 4 batches in 32 bytes per padded pixel.
//   a.x = h2(b0.v00,b0.v01)  a.y = h2(b0.v10,b0.v11)
//   a.z/a.w = batch1, b.* = batches 2,3.
// vXY = img[y0+X][x0+Y], OOB -> 0 (zero border = reference's validity mask).
struct __align__(32) Px { uint4 a, b; };
__device__ Px g_P[NPIX];

__device__ __forceinline__ unsigned pack2(float a, float b) {
    __half2 h = __floats2half2_rn(a, b);
    return *reinterpret_cast<unsigned*>(&h);
}
__device__ __forceinline__ float2 unpack2(unsigned u) {
    __half2 h = *reinterpret_cast<__half2*>(&u);
    return __half22float2(h);
}

// 256-bit global load (sm_100+).
__device__ __forceinline__ void ldg256(const Px* p, uint4& a, uint4& b) {
    asm volatile("ld.global.nc.v8.u32 {%0,%1,%2,%3,%4,%5,%6,%7}, [%8];"
                 : "=r"(a.x), "=r"(a.y), "=r"(a.z), "=r"(a.w),
                   "=r"(b.x), "=r"(b.y), "=r"(b.z), "=r"(b.w)
                 : "l"(p));
}

// Prep: one thread per (pixel, batch). 4 scalar loads, one coalesced 8B store.
// Thread t -> pixel idx = t>>2, batch b = t&3; stores the b-th uint2 of Px.
__global__ __launch_bounds__(256) void prep_kernel(const float* __restrict__ imgs)
{
    int t = blockIdx.x * blockDim.x + threadIdx.x;
    if (t >= NPIX * NB) return;
    const int b   = t & 3;
    const int idx = t >> 2;
    const int xp = idx % PW;
    const int yp = idx / PW;
    const int yt = yp - 1, yb = yp;
    const int xl = xp - 1, xr = xp;

    const float* im = imgs + (size_t)b * RES * RES;
    const bool vt = ((unsigned)yt < RES), vb = ((unsigned)yb < RES);
    const bool vl = ((unsigned)xl < RES), vr = ((unsigned)xr < RES);
    const float v00 = (vt && vl) ? __ldg(im + yt * RES + xl) : 0.0f;
    const float v01 = (vt && vr) ? __ldg(im + yt * RES + xr) : 0.0f;
    const float v10 = (vb && vl) ? __ldg(im + yb * RES + xl) : 0.0f;
    const float v11 = (vb && vr) ? __ldg(im + yb * RES + xr) : 0.0f;

    uint2 w;
    w.x = pack2(v00, v01);
    w.y = pack2(v10, v11);
    reinterpret_cast<uint2*>(&g_P[idx])[b] = w;
}

// fp32 bilerp from packed (v00,v01)/(v10,v11) words.
__device__ __forceinline__ void bilerp_acc(unsigned top, unsigned bot,
                                           float wx, float wy, float& acc)
{
    const float2 T = unpack2(top);
    const float2 B = unpack2(bot);
    const float ft = fmaf(wx, T.y - T.x, T.x);
    const float fb = fmaf(wx, B.y - B.x, B.x);
    acc += fmaf(wy, fb - ft, ft);
}

// Block = 256 threads (8 warps). Warp tile: 8 rays x 4 t-phases, 64 iters.
// Grid: (angle, ray group) = (180, 4). Direct stores, no atomics.
__global__ __launch_bounds__(256) void radon_kernel(
    const float* __restrict__ angles,
    const float* __restrict__ rays,
    float* __restrict__ out)
{
    const int tid  = threadIdx.x;
    const int lane = tid & 31;
    const int warp = tid >> 5;        // 0..7
    const int r8   = lane & 7;        // ray within warp tile
    const int t4   = lane >> 3;       // t-phase 0..3
    const int a    = blockIdx.x;      // angle
    const int rg   = blockIdx.y;      // ray group 0..3
    const int ray  = rg * 64 + warp * 8 + r8;

    const float4 r4 = __ldg(reinterpret_cast<const float4*>(rays) + ray);
    float s, c;
    sincosf(__ldg(angles + a), &s, &c);

    const float rsx = r4.x * c - r4.y * s;
    const float rsy = r4.x * s + r4.y * c;
    const float dx  = (r4.z * c - r4.w * s) - rsx;
    const float dy  = (r4.z * s + r4.w * c) - rsy;

    const float inv_n = 1.0f / RES;
    const float tp = (float)t4 + 0.5f;
    // +128.5 folds image-center offset (127.5) and the +1 padding shift.
    float gx = rsx + 128.5f + dx * inv_n * tp;
    float gy = rsy + 128.5f + dy * inv_n * tp;
    const float sx4 = dx * inv_n * 4.0f;
    const float sy4 = dy * inv_n * 4.0f;

    float acc0 = 0.f, acc1 = 0.f, acc2 = 0.f, acc3 = 0.f;

    #pragma unroll 8
    for (int i = 0; i < 64; ++i) {
        const int x0 = __float2int_rd(gx);
        const int y0 = __float2int_rd(gy);
        const float wx = gx - (float)x0;
        const float wy = gy - (float)y0;
        const int idx = y0 * PW + x0;

        uint4 qa, qb;
        ldg256(g_P + idx, qa, qb);

        bilerp_acc(qa.x, qa.y, wx, wy, acc0);
        bilerp_acc(qa.z, qa.w, wx, wy, acc1);
        bilerp_acc(qb.x, qb.y, wx, wy, acc2);
        bilerp_acc(qb.z, qb.w, wx, wy, acc3);

        gx += sx4;
        gy += sy4;
    }

    // Reduce the 4 t-phases of each ray (lanes l, l+8, l+16, l+24).
    acc0 += __shfl_xor_sync(0xFFFFFFFFu, acc0, 8);
    acc0 += __shfl_xor_sync(0xFFFFFFFFu, acc0, 16);
    acc1 += __shfl_xor_sync(0xFFFFFFFFu, acc1, 8);
    acc1 += __shfl_xor_sync(0xFFFFFFFFu, acc1, 16);
    acc2 += __shfl_xor_sync(0xFFFFFFFFu, acc2, 8);
    acc2 += __shfl_xor_sync(0xFFFFFFFFu, acc2, 16);
    acc3 += __shfl_xor_sync(0xFFFFFFFFu, acc3, 8);
    acc3 += __shfl_xor_sync(0xFFFFFFFFu, acc3, 16);

    if (t4 == 0) {
        const float step = (r4.w - r4.y) * inv_n;   // L / n_steps
        const int base = a * RES + ray;
        out[0 * NA * RES + base] = acc0 * step;
        out[1 * NA * RES + base] = acc1 * step;
        out[2 * NA * RES + base] = acc2 * step;
        out[3 * NA * RES + base] = acc3 * step;
    }
}

extern "C" void kernel_launch(void* const* d_in, const int* in_sizes, int n_in,
                              void* d_out, int out_size)
{
    const float* imgs   = (const float*)d_in[0];   // [4,256,256]
    const float* angles = (const float*)d_in[1];   // [180]
    const float* rays   = (const float*)d_in[2];   // [256,4]
    float* out          = (float*)d_out;           // [4,180,256]

    prep_kernel<<<(NPIX * NB + 255) / 256, 256>>>(imgs);

    dim3 grid(NA, 4);
    radon_kernel<<<grid, 256>>>(angles, rays, out);
}